// round 11
// baseline (speedup 1.0000x reference)
#include <cuda_runtime.h>
#include <cuda_fp16.h>
#include <cstdint>

// Problem constants (from reference)
#define N_NODES 50000
#define N_EDGES 800000
#define D_IN    128
#define D_OUT   128

// Scratch: support = X @ W stored as fp16 (12.8 MB).
__device__ __half g_support[(size_t)N_NODES * D_OUT];

// ---------------------------------------------------------------------------
// Kernel 1: tf32 tensor-core GEMM  support[M,128] = X[M,128] @ W[128,128]
// BM=64 this round: halves per-CTA work/registers -> 3 CTAs/SM, 782 CTAs,
// better wave balance (1.76 waves @76% tail vs 1.32 @32%).
// 256 threads = 8 warps in 2(m) x 4(n); warp tile 32x32 = 2mt x 4nt m16n8k8.
// ---------------------------------------------------------------------------
#define BM   64
#define BKT  32
#define APAD 4
#define BPAD 4

__device__ __forceinline__ float f2tf32(float x) {
    uint32_t u;
    asm("cvt.rna.tf32.f32 %0, %1;" : "=r"(u) : "f"(x));
    return __uint_as_float(u);
}

__device__ __forceinline__ void mma_tf32(float* c, const uint32_t* a,
                                         uint32_t b0, uint32_t b1) {
    asm volatile(
        "mma.sync.aligned.m16n8k8.row.col.f32.tf32.tf32.f32 "
        "{%0,%1,%2,%3}, {%4,%5,%6,%7}, {%8,%9}, {%0,%1,%2,%3};\n"
        : "+f"(c[0]), "+f"(c[1]), "+f"(c[2]), "+f"(c[3])
        : "r"(a[0]), "r"(a[1]), "r"(a[2]), "r"(a[3]), "r"(b0), "r"(b1));
}

__global__ __launch_bounds__(256, 3) void gemm_tc_kernel(const float* __restrict__ X,
                                                         const float* __restrict__ W) {
    __shared__ float As[BM][BKT + APAD];       // 64 x 36   (9.2 KB)
    __shared__ float Bs[BKT][D_OUT + BPAD];    // 32 x 132  (16.9 KB)

    const int tid  = threadIdx.x;
    const int wid  = tid >> 5;
    const int lane = tid & 31;
    const int block_row = blockIdx.x * BM;

    const int warp_m = (wid & 1) * 32;   // 0,32
    const int warp_n = (wid >> 1) * 32;  // 0,32,64,96
    const int lq = lane >> 2;            // 0..7
    const int lr = lane & 3;             // 0..3

    float acc[2][4][4];
#pragma unroll
    for (int mt = 0; mt < 2; mt++)
#pragma unroll
        for (int nt = 0; nt < 4; nt++)
#pragma unroll
            for (int i = 0; i < 4; i++) acc[mt][nt][i] = 0.0f;

    // Register staging. A tile: 64x32 = 512 float4 -> 2/thread.
    //                   B tile: 32x128 = 1024 float4 -> 4/thread.
    float4 aR[2], bR[4];

#pragma unroll
    for (int i = 0; i < 2; i++) {
        int idx = tid + i * 256;         // 0..511
        int ar  = idx >> 3;              // 0..63
        int ac4 = idx & 7;
        int grow = block_row + ar;
        aR[i] = (grow < N_NODES)
            ? *(const float4*)&X[(size_t)grow * D_IN + ac4 * 4]
            : make_float4(0.f, 0.f, 0.f, 0.f);
    }
#pragma unroll
    for (int i = 0; i < 4; i++) {
        int idx = tid + i * 256;
        int br  = idx >> 5;
        int bc4 = idx & 31;
        bR[i] = *(const float4*)&W[(size_t)br * D_OUT + bc4 * 4];
    }

#pragma unroll 1
    for (int kb = 0; kb < D_IN / BKT; kb++) {
#pragma unroll
        for (int i = 0; i < 2; i++) {
            int idx = tid + i * 256;
            int ar  = idx >> 3;
            int ac4 = (idx & 7) * 4;
            float4 a = aR[i];
            *(float4*)&As[ar][ac4] =
                make_float4(f2tf32(a.x), f2tf32(a.y), f2tf32(a.z), f2tf32(a.w));
        }
#pragma unroll
        for (int i = 0; i < 4; i++) {
            int idx = tid + i * 256;
            int br  = idx >> 5;
            int bc4 = (idx & 31) * 4;
            float4 b = bR[i];
            *(float4*)&Bs[br][bc4] =
                make_float4(f2tf32(b.x), f2tf32(b.y), f2tf32(b.z), f2tf32(b.w));
        }
        __syncthreads();

        if (kb + 1 < D_IN / BKT) {
            int k0 = (kb + 1) * BKT;
#pragma unroll
            for (int i = 0; i < 2; i++) {
                int idx = tid + i * 256;
                int ar  = idx >> 3;
                int ac4 = idx & 7;
                int grow = block_row + ar;
                aR[i] = (grow < N_NODES)
                    ? *(const float4*)&X[(size_t)grow * D_IN + k0 + ac4 * 4]
                    : make_float4(0.f, 0.f, 0.f, 0.f);
            }
#pragma unroll
            for (int i = 0; i < 4; i++) {
                int idx = tid + i * 256;
                int br  = idx >> 5;
                int bc4 = idx & 31;
                bR[i] = *(const float4*)&W[(size_t)(k0 + br) * D_OUT + bc4 * 4];
            }
        }

#pragma unroll
        for (int ks = 0; ks < 4; ks++) {
            const int k0 = ks * 8;
            uint32_t afrag[2][4];
#pragma unroll
            for (int mt = 0; mt < 2; mt++) {
                int row = warp_m + mt * 16 + lq;
                afrag[mt][0] = __float_as_uint(As[row    ][k0 + lr    ]);
                afrag[mt][1] = __float_as_uint(As[row + 8][k0 + lr    ]);
                afrag[mt][2] = __float_as_uint(As[row    ][k0 + lr + 4]);
                afrag[mt][3] = __float_as_uint(As[row + 8][k0 + lr + 4]);
            }
#pragma unroll
            for (int nt = 0; nt < 4; nt++) {
                int n0 = warp_n + nt * 8;
                uint32_t b0 = __float_as_uint(Bs[k0 + lr    ][n0 + lq]);
                uint32_t b1 = __float_as_uint(Bs[k0 + lr + 4][n0 + lq]);
                mma_tf32(acc[0][nt], afrag[0], b0, b1);
                mma_tf32(acc[1][nt], afrag[1], b0, b1);
            }
        }
        __syncthreads();
    }

    // Epilogue: (c0,c1) -> row r0 cols (c,c+1); (c2,c3) -> row r1.
#pragma unroll
    for (int mt = 0; mt < 2; mt++) {
        int r0 = block_row + warp_m + mt * 16 + lq;
        int r1 = r0 + 8;
#pragma unroll
        for (int nt = 0; nt < 4; nt++) {
            int c = warp_n + nt * 8 + lr * 2;
            if (r0 < N_NODES)
                *(__half2*)&g_support[(size_t)r0 * D_OUT + c] =
                    __floats2half2_rn(acc[mt][nt][0], acc[mt][nt][1]);
            if (r1 < N_NODES)
                *(__half2*)&g_support[(size_t)r1 * D_OUT + c] =
                    __floats2half2_rn(acc[mt][nt][2], acc[mt][nt][3]);
        }
    }
}

// ---------------------------------------------------------------------------
// Kernel 2: out[n, :] = bias[:]
// ---------------------------------------------------------------------------
__global__ __launch_bounds__(256) void bias_init_kernel(const float* __restrict__ bias,
                                                        float* __restrict__ out) {
    __shared__ float4 b4[D_OUT / 4];
    if (threadIdx.x < D_OUT / 4)
        b4[threadIdx.x] = *(const float4*)&bias[threadIdx.x * 4];
    __syncthreads();

    size_t total4 = (size_t)N_NODES * D_OUT / 4;
    size_t idx = (size_t)blockIdx.x * blockDim.x + threadIdx.x;
    size_t stride = (size_t)gridDim.x * blockDim.x;
    for (; idx < total4; idx += stride) {
        ((float4*)out)[idx] = b4[idx & (D_OUT / 4 - 1)];
    }
}

// ---------------------------------------------------------------------------
// Kernel 3: SpMM scatter.  Unroll-4 gathers (MLP) kept from R10.
// NEW: sorted-dst exclusivity. A segment that starts AND ends strictly inside
// a warp's chunk is owned solely by this warp (sorted dst cannot reappear
// elsewhere), so its flush is a plain STG.128 of (bias + acc) — no atomic.
// Only the chunk's first segment and final segment (potentially shared with
// neighboring chunks) use atomicAdd onto the bias-initialized output.
// This removes ~80% of the ~8M f32 L2-atomic lane-ops that R10 showed are
// contending with the gathers.
// ---------------------------------------------------------------------------
#define EDGES_PER_WARP 128

__global__ __launch_bounds__(256) void spmm_kernel(const int* __restrict__ src,
                                                   const int* __restrict__ dst,
                                                   const float* __restrict__ val,
                                                   const float* __restrict__ bias,
                                                   float* __restrict__ out) {
    const int warp_id = (blockIdx.x * blockDim.x + threadIdx.x) >> 5;
    const int lane    = threadIdx.x & 31;
    const int lane4   = lane * 4;

    const int e0 = warp_id * EDGES_PER_WARP;
    if (e0 >= N_EDGES) return;
    const int e1 = e0 + EDGES_PER_WARP;   // always full: 800000 % 128 == 0

    const float4 bias4 = *(const float4*)&bias[lane4];

    float4 acc = make_float4(0.f, 0.f, 0.f, 0.f);
    const int first_dst = dst[e0];
    int cur_dst = first_dst;

    const uint2 zero2 = make_uint2(0u, 0u);

    for (int e = e0; e < e1; e += 4) {
        // Vector metadata loads (16B aligned: e % 4 == 0).
        const int4   s4 = *(const int4*)&src[e];
        const int4   d4 = *(const int4*)&dst[e];
        const float4 v4 = *(const float4*)&val[e];

        // Issue all 4 independent gathers up front -> MLP=4.
        uint2 g0 = ((unsigned)s4.x < N_NODES)
            ? *(const uint2*)&g_support[(size_t)s4.x * D_OUT + lane4] : zero2;
        uint2 g1 = ((unsigned)s4.y < N_NODES)
            ? *(const uint2*)&g_support[(size_t)s4.y * D_OUT + lane4] : zero2;
        uint2 g2 = ((unsigned)s4.z < N_NODES)
            ? *(const uint2*)&g_support[(size_t)s4.z * D_OUT + lane4] : zero2;
        uint2 g3 = ((unsigned)s4.w < N_NODES)
            ? *(const uint2*)&g_support[(size_t)s4.w * D_OUT + lane4] : zero2;

        const int   ds[4] = {d4.x, d4.y, d4.z, d4.w};
        const float vs[4] = {v4.x, v4.y, v4.z, v4.w};
        const uint2 gs[4] = {g0, g1, g2, g3};

#pragma unroll
        for (int i = 0; i < 4; i++) {
            if (ds[i] != cur_dst) {
                if ((unsigned)cur_dst < N_NODES) {
                    if (cur_dst == first_dst) {
                        // May be shared with the previous chunk -> atomic.
                        float* o = &out[(size_t)cur_dst * D_OUT + lane4];
                        atomicAdd(&o[0], acc.x);
                        atomicAdd(&o[1], acc.y);
                        atomicAdd(&o[2], acc.z);
                        atomicAdd(&o[3], acc.w);
                    } else {
                        // Interior segment: exclusively owned -> plain store.
                        *(float4*)&out[(size_t)cur_dst * D_OUT + lane4] =
                            make_float4(acc.x + bias4.x, acc.y + bias4.y,
                                        acc.z + bias4.z, acc.w + bias4.w);
                    }
                }
                acc = make_float4(0.f, 0.f, 0.f, 0.f);
                cur_dst = ds[i];
            }
            float2 f0 = __half22float2(*(const __half2*)&gs[i].x);
            float2 f1 = __half22float2(*(const __half2*)&gs[i].y);
            float v = vs[i];
            acc.x += v * f0.x;
            acc.y += v * f0.y;
            acc.z += v * f1.x;
            acc.w += v * f1.y;
        }
    }

    // Final segment: may extend into the next chunk -> atomic.
    if ((unsigned)cur_dst < N_NODES) {
        float* o = &out[(size_t)cur_dst * D_OUT + lane4];
        atomicAdd(&o[0], acc.x);
        atomicAdd(&o[1], acc.y);
        atomicAdd(&o[2], acc.z);
        atomicAdd(&o[3], acc.w);
    }
}

// ---------------------------------------------------------------------------
// Launch
// Inputs (metadata order): x, adj_src, adj_dst, adj_val, weight, bias
// ---------------------------------------------------------------------------
extern "C" void kernel_launch(void* const* d_in, const int* in_sizes, int n_in,
                              void* d_out, int out_size) {
    const float* x      = (const float*)d_in[0];
    const int*   adjsrc = (const int*)d_in[1];
    const int*   adjdst = (const int*)d_in[2];
    const float* adjval = (const float*)d_in[3];
    const float* weight = (const float*)d_in[4];
    const float* bias   = (const float*)d_in[5];
    float*       out    = (float*)d_out;

    // 1) support = X @ W  (tf32 tensor cores, fp16 output)
    int gemm_blocks = (N_NODES + BM - 1) / BM;   // 782
    gemm_tc_kernel<<<gemm_blocks, 256>>>(x, weight);

    // 2) out = bias (broadcast) — needed for zero-degree and boundary nodes.
    bias_init_kernel<<<1184, 256>>>(bias, out);

    // 3) out += segment_sum(val * support[src], dst)
    int n_warps  = (N_EDGES + EDGES_PER_WARP - 1) / EDGES_PER_WARP;  // 6250
    int n_blocks = (n_warps + 7) / 8;                                // 782
    spmm_kernel<<<n_blocks, 256>>>(adjsrc, adjdst, adjval, bias, out);
}

// round 12
// speedup vs baseline: 1.3060x; 1.3060x over previous
#include <cuda_runtime.h>
#include <cuda_fp16.h>
#include <cstdint>

// Problem constants (from reference)
#define N_NODES 50000
#define N_EDGES 800000
#define D_IN    128
#define D_OUT   128

// Scratch: support = X @ W stored as fp16 (12.8 MB).
__device__ __half g_support[(size_t)N_NODES * D_OUT];
// CSR row pointers built from the sorted adj_dst (200 KB).
__device__ int g_row_ptr[N_NODES + 1];

// ---------------------------------------------------------------------------
// Kernel 1: tf32 tensor-core GEMM  support[M,128] = X[M,128] @ W[128,128]
// BM=128 (reverted to the measured 25.8us configuration from R10).
// ---------------------------------------------------------------------------
#define BM   128
#define BKT  32
#define APAD 4
#define BPAD 4

__device__ __forceinline__ float f2tf32(float x) {
    uint32_t u;
    asm("cvt.rna.tf32.f32 %0, %1;" : "=r"(u) : "f"(x));
    return __uint_as_float(u);
}

__device__ __forceinline__ void mma_tf32(float* c, const uint32_t* a,
                                         uint32_t b0, uint32_t b1) {
    asm volatile(
        "mma.sync.aligned.m16n8k8.row.col.f32.tf32.tf32.f32 "
        "{%0,%1,%2,%3}, {%4,%5,%6,%7}, {%8,%9}, {%0,%1,%2,%3};\n"
        : "+f"(c[0]), "+f"(c[1]), "+f"(c[2]), "+f"(c[3])
        : "r"(a[0]), "r"(a[1]), "r"(a[2]), "r"(a[3]), "r"(b0), "r"(b1));
}

__global__ __launch_bounds__(256, 2) void gemm_tc_kernel(const float* __restrict__ X,
                                                         const float* __restrict__ W) {
    __shared__ float As[BM][BKT + APAD];     // 128 x 36
    __shared__ float Bs[BKT][D_OUT + BPAD];  // 32 x 132

    const int tid  = threadIdx.x;
    const int wid  = tid >> 5;
    const int lane = tid & 31;
    const int block_row = blockIdx.x * BM;

    const int warp_m = (wid & 3) * 32;
    const int warp_n = (wid >> 2) * 64;
    const int lq = lane >> 2;
    const int lr = lane & 3;

    float acc[2][8][4];
#pragma unroll
    for (int mt = 0; mt < 2; mt++)
#pragma unroll
        for (int nt = 0; nt < 8; nt++)
#pragma unroll
            for (int i = 0; i < 4; i++) acc[mt][nt][i] = 0.0f;

    float4 aR[4], bR[4];

#pragma unroll
    for (int i = 0; i < 4; i++) {
        int idx = tid + i * 256;
        int ar  = idx >> 3;
        int ac4 = idx & 7;
        int grow = block_row + ar;
        aR[i] = (grow < N_NODES)
            ? *(const float4*)&X[(size_t)grow * D_IN + ac4 * 4]
            : make_float4(0.f, 0.f, 0.f, 0.f);
        int br  = idx >> 5;
        int bc4 = idx & 31;
        bR[i] = *(const float4*)&W[(size_t)br * D_OUT + bc4 * 4];
    }

#pragma unroll 1
    for (int kb = 0; kb < D_IN / BKT; kb++) {
#pragma unroll
        for (int i = 0; i < 4; i++) {
            int idx = tid + i * 256;
            int ar  = idx >> 3;
            int ac4 = (idx & 7) * 4;
            float4 a = aR[i];
            *(float4*)&As[ar][ac4] =
                make_float4(f2tf32(a.x), f2tf32(a.y), f2tf32(a.z), f2tf32(a.w));
            int br  = idx >> 5;
            int bc4 = (idx & 31) * 4;
            float4 b = bR[i];
            *(float4*)&Bs[br][bc4] =
                make_float4(f2tf32(b.x), f2tf32(b.y), f2tf32(b.z), f2tf32(b.w));
        }
        __syncthreads();

        if (kb + 1 < D_IN / BKT) {
            int k0 = (kb + 1) * BKT;
#pragma unroll
            for (int i = 0; i < 4; i++) {
                int idx = tid + i * 256;
                int ar  = idx >> 3;
                int ac4 = idx & 7;
                int grow = block_row + ar;
                aR[i] = (grow < N_NODES)
                    ? *(const float4*)&X[(size_t)grow * D_IN + k0 + ac4 * 4]
                    : make_float4(0.f, 0.f, 0.f, 0.f);
                int br  = idx >> 5;
                int bc4 = idx & 31;
                bR[i] = *(const float4*)&W[(size_t)(k0 + br) * D_OUT + bc4 * 4];
            }
        }

#pragma unroll
        for (int ks = 0; ks < 4; ks++) {
            const int k0 = ks * 8;
            uint32_t afrag[2][4];
#pragma unroll
            for (int mt = 0; mt < 2; mt++) {
                int row = warp_m + mt * 16 + lq;
                afrag[mt][0] = __float_as_uint(As[row    ][k0 + lr    ]);
                afrag[mt][1] = __float_as_uint(As[row + 8][k0 + lr    ]);
                afrag[mt][2] = __float_as_uint(As[row    ][k0 + lr + 4]);
                afrag[mt][3] = __float_as_uint(As[row + 8][k0 + lr + 4]);
            }
#pragma unroll
            for (int nt = 0; nt < 8; nt++) {
                int n0 = warp_n + nt * 8;
                uint32_t b0 = __float_as_uint(Bs[k0 + lr    ][n0 + lq]);
                uint32_t b1 = __float_as_uint(Bs[k0 + lr + 4][n0 + lq]);
                mma_tf32(acc[0][nt], afrag[0], b0, b1);
                mma_tf32(acc[1][nt], afrag[1], b0, b1);
            }
        }
        __syncthreads();
    }

#pragma unroll
    for (int mt = 0; mt < 2; mt++) {
        int r0 = block_row + warp_m + mt * 16 + lq;
        int r1 = r0 + 8;
#pragma unroll
        for (int nt = 0; nt < 8; nt++) {
            int c = warp_n + nt * 8 + lr * 2;
            if (r0 < N_NODES)
                *(__half2*)&g_support[(size_t)r0 * D_OUT + c] =
                    __floats2half2_rn(acc[mt][nt][0], acc[mt][nt][1]);
            if (r1 < N_NODES)
                *(__half2*)&g_support[(size_t)r1 * D_OUT + c] =
                    __floats2half2_rn(acc[mt][nt][2], acc[mt][nt][3]);
        }
    }
}

// ---------------------------------------------------------------------------
// Kernel 2: build CSR row_ptr from SORTED adj_dst.
// row_ptr[n] = first edge index e with dst[e] >= n.  O(E) streaming; gap
// loops are ~always length 1 (uniform random dsts -> expected absent nodes
// ~1e-7 * N).
// ---------------------------------------------------------------------------
__global__ __launch_bounds__(256) void build_rowptr_kernel(const int* __restrict__ dst) {
    int e = blockIdx.x * blockDim.x + threadIdx.x;
    if (e >= N_EDGES) return;

    int d = dst[e];
    if (d < 0) d = 0;
    if (d > N_NODES - 1) d = N_NODES - 1;

    if (e == 0) {
        for (int n = 0; n <= d; n++) g_row_ptr[n] = 0;
    } else {
        int dp = dst[e - 1];
        if (dp < 0) dp = 0;
        if (dp > N_NODES - 1) dp = N_NODES - 1;
        for (int n = dp + 1; n <= d; n++) g_row_ptr[n] = e;
    }
    if (e == N_EDGES - 1) {
        for (int n = d + 1; n <= N_NODES; n++) g_row_ptr[n] = N_EDGES;
    }
}

// ---------------------------------------------------------------------------
// Kernel 3: CSR SpMM.  One warp per dst node:
//   out[n,:] = bias + sum_{e in [row_ptr[n], row_ptr[n+1])} val[e]*support[src[e],:]
// No atomics, no dst loads in the mainloop, no separate bias-init (degree-0
// nodes store pure bias).  Gathers batched 4-wide for MLP.
// ---------------------------------------------------------------------------
__global__ __launch_bounds__(256) void spmm_csr_kernel(const int* __restrict__ src,
                                                       const float* __restrict__ val,
                                                       const float* __restrict__ bias,
                                                       float* __restrict__ out) {
    const int warp_id = (blockIdx.x * blockDim.x + threadIdx.x) >> 5;
    const int lane    = threadIdx.x & 31;
    const int lane4   = lane * 4;

    if (warp_id >= N_NODES) return;
    const int n  = warp_id;
    const int r0 = g_row_ptr[n];
    const int r1 = g_row_ptr[n + 1];

    const float4 bias4 = *(const float4*)&bias[lane4];
    float4 acc = make_float4(0.f, 0.f, 0.f, 0.f);

    const uint2 zero2 = make_uint2(0u, 0u);

    int e = r0;
    // Batches of 4: issue all metadata loads, then all gathers (MLP=4).
    for (; e + 4 <= r1; e += 4) {
        int   s0 = src[e],     s1 = src[e + 1], s2 = src[e + 2], s3 = src[e + 3];
        float v0 = val[e],     v1 = val[e + 1], v2 = val[e + 2], v3 = val[e + 3];

        uint2 g0 = ((unsigned)s0 < N_NODES)
            ? *(const uint2*)&g_support[(size_t)s0 * D_OUT + lane4] : zero2;
        uint2 g1 = ((unsigned)s1 < N_NODES)
            ? *(const uint2*)&g_support[(size_t)s1 * D_OUT + lane4] : zero2;
        uint2 g2 = ((unsigned)s2 < N_NODES)
            ? *(const uint2*)&g_support[(size_t)s2 * D_OUT + lane4] : zero2;
        uint2 g3 = ((unsigned)s3 < N_NODES)
            ? *(const uint2*)&g_support[(size_t)s3 * D_OUT + lane4] : zero2;

        float2 f;
        f = __half22float2(*(const __half2*)&g0.x); acc.x += v0 * f.x; acc.y += v0 * f.y;
        f = __half22float2(*(const __half2*)&g0.y); acc.z += v0 * f.x; acc.w += v0 * f.y;
        f = __half22float2(*(const __half2*)&g1.x); acc.x += v1 * f.x; acc.y += v1 * f.y;
        f = __half22float2(*(const __half2*)&g1.y); acc.z += v1 * f.x; acc.w += v1 * f.y;
        f = __half22float2(*(const __half2*)&g2.x); acc.x += v2 * f.x; acc.y += v2 * f.y;
        f = __half22float2(*(const __half2*)&g2.y); acc.z += v2 * f.x; acc.w += v2 * f.y;
        f = __half22float2(*(const __half2*)&g3.x); acc.x += v3 * f.x; acc.y += v3 * f.y;
        f = __half22float2(*(const __half2*)&g3.y); acc.z += v3 * f.x; acc.w += v3 * f.y;
    }
    // Tail (< 4 edges).
    for (; e < r1; e++) {
        int   s = src[e];
        float v = val[e];
        uint2 g = ((unsigned)s < N_NODES)
            ? *(const uint2*)&g_support[(size_t)s * D_OUT + lane4] : zero2;
        float2 f0 = __half22float2(*(const __half2*)&g.x);
        float2 f1 = __half22float2(*(const __half2*)&g.y);
        acc.x += v * f0.x;
        acc.y += v * f0.y;
        acc.z += v * f1.x;
        acc.w += v * f1.y;
    }

    *(float4*)&out[(size_t)n * D_OUT + lane4] =
        make_float4(acc.x + bias4.x, acc.y + bias4.y,
                    acc.z + bias4.z, acc.w + bias4.w);
}

// ---------------------------------------------------------------------------
// Launch
// Inputs (metadata order): x, adj_src, adj_dst, adj_val, weight, bias
// ---------------------------------------------------------------------------
extern "C" void kernel_launch(void* const* d_in, const int* in_sizes, int n_in,
                              void* d_out, int out_size) {
    const float* x      = (const float*)d_in[0];
    const int*   adjsrc = (const int*)d_in[1];
    const int*   adjdst = (const int*)d_in[2];
    const float* adjval = (const float*)d_in[3];
    const float* weight = (const float*)d_in[4];
    const float* bias   = (const float*)d_in[5];
    float*       out    = (float*)d_out;

    // 1) row_ptr from sorted adj_dst
    build_rowptr_kernel<<<(N_EDGES + 255) / 256, 256>>>(adjdst);

    // 2) support = X @ W  (tf32 tensor cores, fp16 output)
    int gemm_blocks = (N_NODES + BM - 1) / BM;   // 391
    gemm_tc_kernel<<<gemm_blocks, 256>>>(x, weight);

    // 3) out[n,:] = bias + CSR-row reduction  (one warp per node)
    int n_blocks = (N_NODES * 32 + 255) / 256;   // 6250
    spmm_csr_kernel<<<n_blocks, 256>>>(adjsrc, adjval, bias, out);
}

// round 13
// speedup vs baseline: 1.5805x; 1.2101x over previous
#include <cuda_runtime.h>
#include <cuda_fp16.h>
#include <cstdint>

// Problem constants (from reference)
#define N_NODES 50000
#define N_EDGES 800000
#define D_IN    128
#define D_OUT   128

// Scratch: support = X @ W stored as fp16 (12.8 MB).
__device__ __half g_support[(size_t)N_NODES * D_OUT];
// CSR row pointers built from the sorted adj_dst (200 KB).
__device__ int g_row_ptr[N_NODES + 1];

// ---------------------------------------------------------------------------
// Kernel 1: fp16 tensor-core GEMM  support[M,128] = X[M,128] @ W[128,128]
// BM=128, BK=32, 256 threads = 8 warps in 4(m) x 2(n); warp tile 32x64.
// fp16 inputs (same 10-bit mantissa as tf32), fp32 accumulate, ldmatrix
// fragment loads (replaces ~96 scalar LDS per slab with 12 ldmatrix.x4).
// ---------------------------------------------------------------------------
#define BM    128
#define BKT   32
#define APADH 8   // As stride 40 halves = 80B  (ldmatrix phase conflict-free)
#define BPADH 8   // Bs stride 136 halves = 272B (ldmatrix phase conflict-free)

__device__ __forceinline__ uint32_t smem_u32(const void* p) {
    return (uint32_t)__cvta_generic_to_shared(p);
}

__device__ __forceinline__ void ldm_x4(uint32_t* r, const void* p) {
    uint32_t a = smem_u32(p);
    asm volatile("ldmatrix.sync.aligned.m8n8.x4.shared.b16 {%0,%1,%2,%3}, [%4];"
                 : "=r"(r[0]), "=r"(r[1]), "=r"(r[2]), "=r"(r[3]) : "r"(a));
}

__device__ __forceinline__ void ldm_x4_trans(uint32_t* r, const void* p) {
    uint32_t a = smem_u32(p);
    asm volatile("ldmatrix.sync.aligned.m8n8.x4.trans.shared.b16 {%0,%1,%2,%3}, [%4];"
                 : "=r"(r[0]), "=r"(r[1]), "=r"(r[2]), "=r"(r[3]) : "r"(a));
}

__device__ __forceinline__ void mma_f16(float* c, const uint32_t* a,
                                        uint32_t b0, uint32_t b1) {
    asm volatile(
        "mma.sync.aligned.m16n8k16.row.col.f32.f16.f16.f32 "
        "{%0,%1,%2,%3}, {%4,%5,%6,%7}, {%8,%9}, {%0,%1,%2,%3};\n"
        : "+f"(c[0]), "+f"(c[1]), "+f"(c[2]), "+f"(c[3])
        : "r"(a[0]), "r"(a[1]), "r"(a[2]), "r"(a[3]), "r"(b0), "r"(b1));
}

__global__ __launch_bounds__(256, 2) void gemm_tc_kernel(const float* __restrict__ X,
                                                         const float* __restrict__ W) {
    __shared__ __half As[BM][BKT + APADH];     // 128 x 40 halves (10.2 KB)
    __shared__ __half Bs[BKT][D_OUT + BPADH];  // 32 x 136 halves (8.7 KB)

    const int tid  = threadIdx.x;
    const int wid  = tid >> 5;
    const int lane = tid & 31;
    const int block_row = blockIdx.x * BM;

    const int warp_m = (wid & 3) * 32;   // 0,32,64,96
    const int warp_n = (wid >> 2) * 64;  // 0,64
    const int lq = lane >> 2;            // 0..7 (C-fragment row group)
    const int lr = lane & 3;             // 0..3
    const int quad = lane >> 3;          // 0..3 (ldmatrix matrix select)
    const int rin  = lane & 7;           // 0..7 (ldmatrix row-in-matrix)

    float acc[2][8][4];
#pragma unroll
    for (int mt = 0; mt < 2; mt++)
#pragma unroll
        for (int nt = 0; nt < 8; nt++)
#pragma unroll
            for (int i = 0; i < 4; i++) acc[mt][nt][i] = 0.0f;

    // Register staging: A tile 128x32 fp32 = 4 float4/thread; B same.
    float4 aR[4], bR[4];

#pragma unroll
    for (int i = 0; i < 4; i++) {
        int idx = tid + i * 256;
        int ar  = idx >> 3;          // 0..127
        int ac4 = idx & 7;           // float4 index in row
        int grow = block_row + ar;
        aR[i] = (grow < N_NODES)
            ? *(const float4*)&X[(size_t)grow * D_IN + ac4 * 4]
            : make_float4(0.f, 0.f, 0.f, 0.f);
        int br  = idx >> 5;          // 0..31
        int bc4 = idx & 31;
        bR[i] = *(const float4*)&W[(size_t)br * D_OUT + bc4 * 4];
    }

#pragma unroll 1
    for (int kb = 0; kb < D_IN / BKT; kb++) {
        // Convert fp32 -> fp16 and store staged tiles (4 halves = uint2 each).
#pragma unroll
        for (int i = 0; i < 4; i++) {
            int idx = tid + i * 256;
            int ar  = idx >> 3;
            int ac  = (idx & 7) * 4;
            float4 a = aR[i];
            __half2 ha0 = __floats2half2_rn(a.x, a.y);
            __half2 ha1 = __floats2half2_rn(a.z, a.w);
            uint2 pa = make_uint2(*(uint32_t*)&ha0, *(uint32_t*)&ha1);
            *(uint2*)&As[ar][ac] = pa;

            int br  = idx >> 5;
            int bc  = (idx & 31) * 4;
            float4 b = bR[i];
            __half2 hb0 = __floats2half2_rn(b.x, b.y);
            __half2 hb1 = __floats2half2_rn(b.z, b.w);
            uint2 pb = make_uint2(*(uint32_t*)&hb0, *(uint32_t*)&hb1);
            *(uint2*)&Bs[br][bc] = pb;
        }
        __syncthreads();

        // Prefetch next slab while MMAs run.
        if (kb + 1 < D_IN / BKT) {
            int k0 = (kb + 1) * BKT;
#pragma unroll
            for (int i = 0; i < 4; i++) {
                int idx = tid + i * 256;
                int ar  = idx >> 3;
                int ac4 = idx & 7;
                int grow = block_row + ar;
                aR[i] = (grow < N_NODES)
                    ? *(const float4*)&X[(size_t)grow * D_IN + k0 + ac4 * 4]
                    : make_float4(0.f, 0.f, 0.f, 0.f);
                int br  = idx >> 5;
                int bc4 = idx & 31;
                bR[i] = *(const float4*)&W[(size_t)(k0 + br) * D_OUT + bc4 * 4];
            }
        }

        // 2 k16-steps per BK=32 slab.
#pragma unroll
        for (int ks = 0; ks < 2; ks++) {
            const int k0 = ks * 16;

            // A fragments: ldmatrix.x4 -> {(r,klo),(r+8,klo),(r,khi),(r+8,khi)}
            uint32_t af[2][4];
#pragma unroll
            for (int mt = 0; mt < 2; mt++) {
                const __half* p =
                    &As[warp_m + mt * 16 + (quad & 1) * 8 + rin][k0 + (quad >> 1) * 8];
                ldm_x4(af[mt], p);
            }

            // B fragments: 4x ldmatrix.x4.trans, each covers two n-tiles.
            // matrices: (klo,n0),(khi,n0),(klo,n0+8),(khi,n0+8)
            uint32_t bf[8][2];
#pragma unroll
            for (int np = 0; np < 4; np++) {
                uint32_t r[4];
                const __half* p =
                    &Bs[k0 + (quad & 1) * 8 + rin][warp_n + np * 16 + (quad >> 1) * 8];
                ldm_x4_trans(r, p);
                bf[np * 2    ][0] = r[0];
                bf[np * 2    ][1] = r[1];
                bf[np * 2 + 1][0] = r[2];
                bf[np * 2 + 1][1] = r[3];
            }

#pragma unroll
            for (int nt = 0; nt < 8; nt++) {
                mma_f16(acc[0][nt], af[0], bf[nt][0], bf[nt][1]);
                mma_f16(acc[1][nt], af[1], bf[nt][0], bf[nt][1]);
            }
        }
        __syncthreads();
    }

    // Epilogue: C m16n8 layout -> (c0,c1) row r0 cols (c,c+1); (c2,c3) row r1.
#pragma unroll
    for (int mt = 0; mt < 2; mt++) {
        int r0 = block_row + warp_m + mt * 16 + lq;
        int r1 = r0 + 8;
#pragma unroll
        for (int nt = 0; nt < 8; nt++) {
            int c = warp_n + nt * 8 + lr * 2;
            if (r0 < N_NODES)
                *(__half2*)&g_support[(size_t)r0 * D_OUT + c] =
                    __floats2half2_rn(acc[mt][nt][0], acc[mt][nt][1]);
            if (r1 < N_NODES)
                *(__half2*)&g_support[(size_t)r1 * D_OUT + c] =
                    __floats2half2_rn(acc[mt][nt][2], acc[mt][nt][3]);
        }
    }
}

// ---------------------------------------------------------------------------
// Kernel 2: build CSR row_ptr from SORTED adj_dst, vectorized x4.
// Thread t owns edges [4t, 4t+4); writes row_ptr[n] = e for each boundary.
// ---------------------------------------------------------------------------
__global__ __launch_bounds__(256) void build_rowptr_kernel(const int* __restrict__ dst) {
    int t = blockIdx.x * blockDim.x + threadIdx.x;
    if (t >= N_EDGES / 4) return;
    const int e = t * 4;

    int4 d4 = *(const int4*)&dst[e];
    int d[4] = {d4.x, d4.y, d4.z, d4.w};
#pragma unroll
    for (int i = 0; i < 4; i++) {
        if (d[i] < 0) d[i] = 0;
        if (d[i] > N_NODES - 1) d[i] = N_NODES - 1;
    }

    int dprev;
    if (e == 0) {
        dprev = -1;
    } else {
        dprev = dst[e - 1];
        if (dprev < 0) dprev = 0;
        if (dprev > N_NODES - 1) dprev = N_NODES - 1;
    }

#pragma unroll
    for (int i = 0; i < 4; i++) {
        for (int n = dprev + 1; n <= d[i]; n++) g_row_ptr[n] = e + i;
        dprev = d[i];
    }
    if (e + 4 == N_EDGES) {
        for (int n = d[3] + 1; n <= N_NODES; n++) g_row_ptr[n] = N_EDGES;
    }
}

// ---------------------------------------------------------------------------
// Kernel 3: CSR SpMM (unchanged from the 55.1us kernel).  One warp per node:
//   out[n,:] = bias + sum_{e in row n} val[e] * support[src[e],:]
// No atomics, no dst loads in mainloop, gathers batched 4-wide for MLP.
// ---------------------------------------------------------------------------
__global__ __launch_bounds__(256) void spmm_csr_kernel(const int* __restrict__ src,
                                                       const float* __restrict__ val,
                                                       const float* __restrict__ bias,
                                                       float* __restrict__ out) {
    const int warp_id = (blockIdx.x * blockDim.x + threadIdx.x) >> 5;
    const int lane    = threadIdx.x & 31;
    const int lane4   = lane * 4;

    if (warp_id >= N_NODES) return;
    const int n  = warp_id;
    const int r0 = g_row_ptr[n];
    const int r1 = g_row_ptr[n + 1];

    const float4 bias4 = *(const float4*)&bias[lane4];
    float4 acc = make_float4(0.f, 0.f, 0.f, 0.f);

    const uint2 zero2 = make_uint2(0u, 0u);

    int e = r0;
    for (; e + 4 <= r1; e += 4) {
        int   s0 = src[e],     s1 = src[e + 1], s2 = src[e + 2], s3 = src[e + 3];
        float v0 = val[e],     v1 = val[e + 1], v2 = val[e + 2], v3 = val[e + 3];

        uint2 g0 = ((unsigned)s0 < N_NODES)
            ? *(const uint2*)&g_support[(size_t)s0 * D_OUT + lane4] : zero2;
        uint2 g1 = ((unsigned)s1 < N_NODES)
            ? *(const uint2*)&g_support[(size_t)s1 * D_OUT + lane4] : zero2;
        uint2 g2 = ((unsigned)s2 < N_NODES)
            ? *(const uint2*)&g_support[(size_t)s2 * D_OUT + lane4] : zero2;
        uint2 g3 = ((unsigned)s3 < N_NODES)
            ? *(const uint2*)&g_support[(size_t)s3 * D_OUT + lane4] : zero2;

        float2 f;
        f = __half22float2(*(const __half2*)&g0.x); acc.x += v0 * f.x; acc.y += v0 * f.y;
        f = __half22float2(*(const __half2*)&g0.y); acc.z += v0 * f.x; acc.w += v0 * f.y;
        f = __half22float2(*(const __half2*)&g1.x); acc.x += v1 * f.x; acc.y += v1 * f.y;
        f = __half22float2(*(const __half2*)&g1.y); acc.z += v1 * f.x; acc.w += v1 * f.y;
        f = __half22float2(*(const __half2*)&g2.x); acc.x += v2 * f.x; acc.y += v2 * f.y;
        f = __half22float2(*(const __half2*)&g2.y); acc.z += v2 * f.x; acc.w += v2 * f.y;
        f = __half22float2(*(const __half2*)&g3.x); acc.x += v3 * f.x; acc.y += v3 * f.y;
        f = __half22float2(*(const __half2*)&g3.y); acc.z += v3 * f.x; acc.w += v3 * f.y;
    }
    for (; e < r1; e++) {
        int   s = src[e];
        float v = val[e];
        uint2 g = ((unsigned)s < N_NODES)
            ? *(const uint2*)&g_support[(size_t)s * D_OUT + lane4] : zero2;
        float2 f0 = __half22float2(*(const __half2*)&g.x);
        float2 f1 = __half22float2(*(const __half2*)&g.y);
        acc.x += v * f0.x;
        acc.y += v * f0.y;
        acc.z += v * f1.x;
        acc.w += v * f1.y;
    }

    *(float4*)&out[(size_t)n * D_OUT + lane4] =
        make_float4(acc.x + bias4.x, acc.y + bias4.y,
                    acc.z + bias4.z, acc.w + bias4.w);
}

// ---------------------------------------------------------------------------
// Launch
// Inputs (metadata order): x, adj_src, adj_dst, adj_val, weight, bias
// ---------------------------------------------------------------------------
extern "C" void kernel_launch(void* const* d_in, const int* in_sizes, int n_in,
                              void* d_out, int out_size) {
    const float* x      = (const float*)d_in[0];
    const int*   adjsrc = (const int*)d_in[1];
    const int*   adjdst = (const int*)d_in[2];
    const float* adjval = (const float*)d_in[3];
    const float* weight = (const float*)d_in[4];
    const float* bias   = (const float*)d_in[5];
    float*       out    = (float*)d_out;

    // 1) row_ptr from sorted adj_dst (vectorized x4)
    build_rowptr_kernel<<<(N_EDGES / 4 + 255) / 256, 256>>>(adjdst);

    // 2) support = X @ W  (fp16 tensor cores, fp16 output)
    int gemm_blocks = (N_NODES + BM - 1) / BM;   // 391
    gemm_tc_kernel<<<gemm_blocks, 256>>>(x, weight);

    // 3) out[n,:] = bias + CSR-row reduction  (one warp per node)
    int n_blocks = (N_NODES * 32 + 255) / 256;   // 6250
    spmm_csr_kernel<<<n_blocks, 256>>>(adjsrc, adjval, bias, out);
}

// round 14
// speedup vs baseline: 1.5950x; 1.0092x over previous
#include <cuda_runtime.h>
#include <cuda_fp16.h>
#include <cstdint>

// Problem constants (from reference)
#define N_NODES 50000
#define N_EDGES 800000
#define D_IN    128
#define D_OUT   128

// Scratch: support = X @ W stored as fp16 (12.8 MB).
__device__ __half g_support[(size_t)N_NODES * D_OUT];
// CSR row pointers built from the sorted adj_dst (200 KB).
__device__ int g_row_ptr[N_NODES + 1];

// ---------------------------------------------------------------------------
// Kernel 1: fp16 tensor-core GEMM + fused CSR row_ptr build.
// BM=128, BK=64 (4 syncs instead of 8), 256 threads = 8 warps 4(m) x 2(n).
// fp32 -> fp16 conversion at LDG time (staging stays 32 regs).
// The rowptr work (indep. of GEMM) is issued in the prologue so its DRAM
// latency overlaps the initial tile prefetch.
// ---------------------------------------------------------------------------
#define BM    128
#define BKT   64
#define APADH 8   // As stride 72 halves = 144B  (≡16 mod 128 -> phases conflict-free)
#define BPADH 8   // Bs stride 136 halves = 272B (≡16 mod 128 -> phases conflict-free)

#define GEMM_GRID    ((N_NODES + BM - 1) / BM)      // 391
#define GEMM_NTHREAD (GEMM_GRID * 256)              // 100096
#define N_GROUPS     (N_EDGES / 4)                  // 200000

__device__ __forceinline__ uint32_t smem_u32(const void* p) {
    return (uint32_t)__cvta_generic_to_shared(p);
}

__device__ __forceinline__ void ldm_x4(uint32_t* r, const void* p) {
    uint32_t a = smem_u32(p);
    asm volatile("ldmatrix.sync.aligned.m8n8.x4.shared.b16 {%0,%1,%2,%3}, [%4];"
                 : "=r"(r[0]), "=r"(r[1]), "=r"(r[2]), "=r"(r[3]) : "r"(a));
}

__device__ __forceinline__ void ldm_x4_trans(uint32_t* r, const void* p) {
    uint32_t a = smem_u32(p);
    asm volatile("ldmatrix.sync.aligned.m8n8.x4.trans.shared.b16 {%0,%1,%2,%3}, [%4];"
                 : "=r"(r[0]), "=r"(r[1]), "=r"(r[2]), "=r"(r[3]) : "r"(a));
}

__device__ __forceinline__ void mma_f16(float* c, const uint32_t* a,
                                        uint32_t b0, uint32_t b1) {
    asm volatile(
        "mma.sync.aligned.m16n8k16.row.col.f32.f16.f16.f32 "
        "{%0,%1,%2,%3}, {%4,%5,%6,%7}, {%8,%9}, {%0,%1,%2,%3};\n"
        : "+f"(c[0]), "+f"(c[1]), "+f"(c[2]), "+f"(c[3])
        : "r"(a[0]), "r"(a[1]), "r"(a[2]), "r"(a[3]), "r"(b0), "r"(b1));
}

__device__ __forceinline__ uint2 f4_to_h4(float4 a) {
    __half2 h0 = __floats2half2_rn(a.x, a.y);
    __half2 h1 = __floats2half2_rn(a.z, a.w);
    return make_uint2(*(uint32_t*)&h0, *(uint32_t*)&h1);
}

__device__ __forceinline__ int clamp_node(int d) {
    if (d < 0) d = 0;
    if (d > N_NODES - 1) d = N_NODES - 1;
    return d;
}

// One group = 4 edges of the sorted dst array; writes row_ptr boundaries.
__device__ __forceinline__ void rowptr_group(const int* __restrict__ dst, int t) {
    const int e = t * 4;
    int4 d4 = *(const int4*)&dst[e];
    int d0 = clamp_node(d4.x), d1 = clamp_node(d4.y);
    int d2 = clamp_node(d4.z), d3 = clamp_node(d4.w);

    int dprev = (e == 0) ? -1 : clamp_node(dst[e - 1]);

    for (int n = dprev + 1; n <= d0; n++) g_row_ptr[n] = e;
    for (int n = d0 + 1;    n <= d1; n++) g_row_ptr[n] = e + 1;
    for (int n = d1 + 1;    n <= d2; n++) g_row_ptr[n] = e + 2;
    for (int n = d2 + 1;    n <= d3; n++) g_row_ptr[n] = e + 3;
    if (e + 4 == N_EDGES) {
        for (int n = d3 + 1; n <= N_NODES; n++) g_row_ptr[n] = N_EDGES;
    }
}

__global__ __launch_bounds__(256, 2) void gemm_tc_kernel(const float* __restrict__ X,
                                                         const float* __restrict__ W,
                                                         const int* __restrict__ dst) {
    __shared__ __half As[BM][BKT + APADH];     // 128 x 72 halves (18.4 KB)
    __shared__ __half Bs[BKT][D_OUT + BPADH];  // 64 x 136 halves (17.4 KB)

    const int tid  = threadIdx.x;
    const int wid  = tid >> 5;
    const int lane = tid & 31;
    const int block_row = blockIdx.x * BM;

    const int warp_m = (wid & 3) * 32;   // 0,32,64,96
    const int warp_n = (wid >> 2) * 64;  // 0,64
    const int lq = lane >> 2;            // 0..7
    const int lr = lane & 3;             // 0..3
    const int quad = lane >> 3;          // 0..3
    const int rin  = lane & 7;           // 0..7

    float acc[2][8][4];
#pragma unroll
    for (int mt = 0; mt < 2; mt++)
#pragma unroll
        for (int nt = 0; nt < 8; nt++)
#pragma unroll
            for (int i = 0; i < 4; i++) acc[mt][nt][i] = 0.0f;

    // Staging: A tile 128x64 = 2048 float4 -> 8/thread (as fp16 uint2).
    //          B tile  64x128 = 2048 float4 -> 8/thread.
    uint2 aH[8], bH[8];

    // Prefetch slab kb=0 (convert fp32->fp16 at load).
#pragma unroll
    for (int i = 0; i < 8; i++) {
        int idx = tid + i * 256;         // 0..2047
        int ar  = idx >> 4;              // 0..127
        int ac4 = idx & 15;              // 0..15
        int grow = block_row + ar;
        float4 a = (grow < N_NODES)
            ? *(const float4*)&X[(size_t)grow * D_IN + ac4 * 4]
            : make_float4(0.f, 0.f, 0.f, 0.f);
        aH[i] = f4_to_h4(a);
        int br  = idx >> 5;              // 0..63
        int bc4 = idx & 31;              // 0..31
        bH[i] = f4_to_h4(*(const float4*)&W[(size_t)br * D_OUT + bc4 * 4]);
    }

    // Fused rowptr build: independent of GEMM; its DRAM latency overlaps
    // the tile-prefetch LDGs already in flight.
    {
        int g = blockIdx.x * 256 + tid;          // 0..100095
        rowptr_group(dst, g);
        int g2 = g + GEMM_NTHREAD;
        if (g2 < N_GROUPS) rowptr_group(dst, g2);
    }

#pragma unroll 1
    for (int kb = 0; kb < D_IN / BKT; kb++) {    // 2 slabs
#pragma unroll
        for (int i = 0; i < 8; i++) {
            int idx = tid + i * 256;
            int ar  = idx >> 4;
            int ac  = (idx & 15) * 4;
            *(uint2*)&As[ar][ac] = aH[i];
            int br  = idx >> 5;
            int bc  = (idx & 31) * 4;
            *(uint2*)&Bs[br][bc] = bH[i];
        }
        __syncthreads();

        // Prefetch next slab while MMAs run.
        if (kb + 1 < D_IN / BKT) {
            int k0 = (kb + 1) * BKT;
#pragma unroll
            for (int i = 0; i < 8; i++) {
                int idx = tid + i * 256;
                int ar  = idx >> 4;
                int ac4 = idx & 15;
                int grow = block_row + ar;
                float4 a = (grow < N_NODES)
                    ? *(const float4*)&X[(size_t)grow * D_IN + k0 + ac4 * 4]
                    : make_float4(0.f, 0.f, 0.f, 0.f);
                aH[i] = f4_to_h4(a);
                int br  = idx >> 5;
                int bc4 = idx & 31;
                bH[i] = f4_to_h4(*(const float4*)&W[(size_t)(k0 + br) * D_OUT + bc4 * 4]);
            }
        }

        // 4 k16-steps per BK=64 slab.
#pragma unroll
        for (int ks = 0; ks < 4; ks++) {
            const int k0 = ks * 16;

            uint32_t af[2][4];
#pragma unroll
            for (int mt = 0; mt < 2; mt++) {
                const __half* p =
                    &As[warp_m + mt * 16 + (quad & 1) * 8 + rin][k0 + (quad >> 1) * 8];
                ldm_x4(af[mt], p);
            }

            uint32_t bf[8][2];
#pragma unroll
            for (int np = 0; np < 4; np++) {
                uint32_t r[4];
                const __half* p =
                    &Bs[k0 + (quad & 1) * 8 + rin][warp_n + np * 16 + (quad >> 1) * 8];
                ldm_x4_trans(r, p);
                bf[np * 2    ][0] = r[0];
                bf[np * 2    ][1] = r[1];
                bf[np * 2 + 1][0] = r[2];
                bf[np * 2 + 1][1] = r[3];
            }

#pragma unroll
            for (int nt = 0; nt < 8; nt++) {
                mma_f16(acc[0][nt], af[0], bf[nt][0], bf[nt][1]);
                mma_f16(acc[1][nt], af[1], bf[nt][0], bf[nt][1]);
            }
        }
        __syncthreads();
    }

    // Epilogue: (c0,c1) -> row r0 cols (c,c+1); (c2,c3) -> row r1.
#pragma unroll
    for (int mt = 0; mt < 2; mt++) {
        int r0 = block_row + warp_m + mt * 16 + lq;
        int r1 = r0 + 8;
#pragma unroll
        for (int nt = 0; nt < 8; nt++) {
            int c = warp_n + nt * 8 + lr * 2;
            if (r0 < N_NODES)
                *(__half2*)&g_support[(size_t)r0 * D_OUT + c] =
                    __floats2half2_rn(acc[mt][nt][0], acc[mt][nt][1]);
            if (r1 < N_NODES)
                *(__half2*)&g_support[(size_t)r1 * D_OUT + c] =
                    __floats2half2_rn(acc[mt][nt][2], acc[mt][nt][3]);
        }
    }
}

// ---------------------------------------------------------------------------
// Kernel 2: CSR SpMM (unchanged; at its LTS roofline ~22us).  One warp/node:
//   out[n,:] = bias + sum_{e in row n} val[e] * support[src[e],:]
// ---------------------------------------------------------------------------
__global__ __launch_bounds__(256) void spmm_csr_kernel(const int* __restrict__ src,
                                                       const float* __restrict__ val,
                                                       const float* __restrict__ bias,
                                                       float* __restrict__ out) {
    const int warp_id = (blockIdx.x * blockDim.x + threadIdx.x) >> 5;
    const int lane    = threadIdx.x & 31;
    const int lane4   = lane * 4;

    if (warp_id >= N_NODES) return;
    const int n  = warp_id;
    const int r0 = g_row_ptr[n];
    const int r1 = g_row_ptr[n + 1];

    const float4 bias4 = *(const float4*)&bias[lane4];
    float4 acc = make_float4(0.f, 0.f, 0.f, 0.f);

    const uint2 zero2 = make_uint2(0u, 0u);

    int e = r0;
    for (; e + 4 <= r1; e += 4) {
        int   s0 = src[e],     s1 = src[e + 1], s2 = src[e + 2], s3 = src[e + 3];
        float v0 = val[e],     v1 = val[e + 1], v2 = val[e + 2], v3 = val[e + 3];

        uint2 g0 = ((unsigned)s0 < N_NODES)
            ? *(const uint2*)&g_support[(size_t)s0 * D_OUT + lane4] : zero2;
        uint2 g1 = ((unsigned)s1 < N_NODES)
            ? *(const uint2*)&g_support[(size_t)s1 * D_OUT + lane4] : zero2;
        uint2 g2 = ((unsigned)s2 < N_NODES)
            ? *(const uint2*)&g_support[(size_t)s2 * D_OUT + lane4] : zero2;
        uint2 g3 = ((unsigned)s3 < N_NODES)
            ? *(const uint2*)&g_support[(size_t)s3 * D_OUT + lane4] : zero2;

        float2 f;
        f = __half22float2(*(const __half2*)&g0.x); acc.x += v0 * f.x; acc.y += v0 * f.y;
        f = __half22float2(*(const __half2*)&g0.y); acc.z += v0 * f.x; acc.w += v0 * f.y;
        f = __half22float2(*(const __half2*)&g1.x); acc.x += v1 * f.x; acc.y += v1 * f.y;
        f = __half22float2(*(const __half2*)&g1.y); acc.z += v1 * f.x; acc.w += v1 * f.y;
        f = __half22float2(*(const __half2*)&g2.x); acc.x += v2 * f.x; acc.y += v2 * f.y;
        f = __half22float2(*(const __half2*)&g2.y); acc.z += v2 * f.x; acc.w += v2 * f.y;
        f = __half22float2(*(const __half2*)&g3.x); acc.x += v3 * f.x; acc.y += v3 * f.y;
        f = __half22float2(*(const __half2*)&g3.y); acc.z += v3 * f.x; acc.w += v3 * f.y;
    }
    for (; e < r1; e++) {
        int   s = src[e];
        float v = val[e];
        uint2 g = ((unsigned)s < N_NODES)
            ? *(const uint2*)&g_support[(size_t)s * D_OUT + lane4] : zero2;
        float2 f0 = __half22float2(*(const __half2*)&g.x);
        float2 f1 = __half22float2(*(const __half2*)&g.y);
        acc.x += v * f0.x;
        acc.y += v * f0.y;
        acc.z += v * f1.x;
        acc.w += v * f1.y;
    }

    *(float4*)&out[(size_t)n * D_OUT + lane4] =
        make_float4(acc.x + bias4.x, acc.y + bias4.y,
                    acc.z + bias4.z, acc.w + bias4.w);
}

// ---------------------------------------------------------------------------
// Launch
// Inputs (metadata order): x, adj_src, adj_dst, adj_val, weight, bias
// ---------------------------------------------------------------------------
extern "C" void kernel_launch(void* const* d_in, const int* in_sizes, int n_in,
                              void* d_out, int out_size) {
    const float* x      = (const float*)d_in[0];
    const int*   adjsrc = (const int*)d_in[1];
    const int*   adjdst = (const int*)d_in[2];
    const float* adjval = (const float*)d_in[3];
    const float* weight = (const float*)d_in[4];
    const float* bias   = (const float*)d_in[5];
    float*       out    = (float*)d_out;

    // 1) support = X @ W (fp16 tensor cores) + fused rowptr build
    gemm_tc_kernel<<<GEMM_GRID, 256>>>(x, weight, adjdst);

    // 2) out[n,:] = bias + CSR-row reduction  (one warp per node)
    int n_blocks = (N_NODES * 32 + 255) / 256;   // 6250
    spmm_csr_kernel<<<n_blocks, 256>>>(adjsrc, adjval, bias, out);
}

// round 15
// speedup vs baseline: 1.6368x; 1.0262x over previous
#include <cuda_runtime.h>
#include <cuda_fp16.h>
#include <cstdint>

// Problem constants (from reference)
#define N_NODES 50000
#define N_EDGES 800000
#define D_IN    128
#define D_OUT   128

// Scratch: support = X @ W stored as fp16 (12.8 MB).
__device__ __half g_support[(size_t)N_NODES * D_OUT];
// CSR row pointers built from the sorted adj_dst (200 KB).
__device__ int g_row_ptr[N_NODES + 1];

// ---------------------------------------------------------------------------
// Kernel 1: fp16 tensor-core GEMM + fused CSR row_ptr build.
// (unchanged from the measured 15.8us configuration)
// ---------------------------------------------------------------------------
#define BM    128
#define BKT   64
#define APADH 8
#define BPADH 8

#define GEMM_GRID    ((N_NODES + BM - 1) / BM)      // 391
#define GEMM_NTHREAD (GEMM_GRID * 256)              // 100096
#define N_GROUPS     (N_EDGES / 4)                  // 200000

__device__ __forceinline__ uint32_t smem_u32(const void* p) {
    return (uint32_t)__cvta_generic_to_shared(p);
}

__device__ __forceinline__ void ldm_x4(uint32_t* r, const void* p) {
    uint32_t a = smem_u32(p);
    asm volatile("ldmatrix.sync.aligned.m8n8.x4.shared.b16 {%0,%1,%2,%3}, [%4];"
                 : "=r"(r[0]), "=r"(r[1]), "=r"(r[2]), "=r"(r[3]) : "r"(a));
}

__device__ __forceinline__ void ldm_x4_trans(uint32_t* r, const void* p) {
    uint32_t a = smem_u32(p);
    asm volatile("ldmatrix.sync.aligned.m8n8.x4.trans.shared.b16 {%0,%1,%2,%3}, [%4];"
                 : "=r"(r[0]), "=r"(r[1]), "=r"(r[2]), "=r"(r[3]) : "r"(a));
}

__device__ __forceinline__ void mma_f16(float* c, const uint32_t* a,
                                        uint32_t b0, uint32_t b1) {
    asm volatile(
        "mma.sync.aligned.m16n8k16.row.col.f32.f16.f16.f32 "
        "{%0,%1,%2,%3}, {%4,%5,%6,%7}, {%8,%9}, {%0,%1,%2,%3};\n"
        : "+f"(c[0]), "+f"(c[1]), "+f"(c[2]), "+f"(c[3])
        : "r"(a[0]), "r"(a[1]), "r"(a[2]), "r"(a[3]), "r"(b0), "r"(b1));
}

__device__ __forceinline__ uint2 f4_to_h4(float4 a) {
    __half2 h0 = __floats2half2_rn(a.x, a.y);
    __half2 h1 = __floats2half2_rn(a.z, a.w);
    return make_uint2(*(uint32_t*)&h0, *(uint32_t*)&h1);
}

__device__ __forceinline__ int clamp_node(int d) {
    if (d < 0) d = 0;
    if (d > N_NODES - 1) d = N_NODES - 1;
    return d;
}

__device__ __forceinline__ void rowptr_group(const int* __restrict__ dst, int t) {
    const int e = t * 4;
    int4 d4 = *(const int4*)&dst[e];
    int d0 = clamp_node(d4.x), d1 = clamp_node(d4.y);
    int d2 = clamp_node(d4.z), d3 = clamp_node(d4.w);

    int dprev = (e == 0) ? -1 : clamp_node(dst[e - 1]);

    for (int n = dprev + 1; n <= d0; n++) g_row_ptr[n] = e;
    for (int n = d0 + 1;    n <= d1; n++) g_row_ptr[n] = e + 1;
    for (int n = d1 + 1;    n <= d2; n++) g_row_ptr[n] = e + 2;
    for (int n = d2 + 1;    n <= d3; n++) g_row_ptr[n] = e + 3;
    if (e + 4 == N_EDGES) {
        for (int n = d3 + 1; n <= N_NODES; n++) g_row_ptr[n] = N_EDGES;
    }
}

__global__ __launch_bounds__(256, 2) void gemm_tc_kernel(const float* __restrict__ X,
                                                         const float* __restrict__ W,
                                                         const int* __restrict__ dst) {
    __shared__ __half As[BM][BKT + APADH];     // 128 x 72 halves
    __shared__ __half Bs[BKT][D_OUT + BPADH];  // 64 x 136 halves

    const int tid  = threadIdx.x;
    const int wid  = tid >> 5;
    const int lane = tid & 31;
    const int block_row = blockIdx.x * BM;

    const int warp_m = (wid & 3) * 32;
    const int warp_n = (wid >> 2) * 64;
    const int lq = lane >> 2;
    const int lr = lane & 3;
    const int quad = lane >> 3;
    const int rin  = lane & 7;

    float acc[2][8][4];
#pragma unroll
    for (int mt = 0; mt < 2; mt++)
#pragma unroll
        for (int nt = 0; nt < 8; nt++)
#pragma unroll
            for (int i = 0; i < 4; i++) acc[mt][nt][i] = 0.0f;

    uint2 aH[8], bH[8];

#pragma unroll
    for (int i = 0; i < 8; i++) {
        int idx = tid + i * 256;
        int ar  = idx >> 4;
        int ac4 = idx & 15;
        int grow = block_row + ar;
        float4 a = (grow < N_NODES)
            ? *(const float4*)&X[(size_t)grow * D_IN + ac4 * 4]
            : make_float4(0.f, 0.f, 0.f, 0.f);
        aH[i] = f4_to_h4(a);
        int br  = idx >> 5;
        int bc4 = idx & 31;
        bH[i] = f4_to_h4(*(const float4*)&W[(size_t)br * D_OUT + bc4 * 4]);
    }

    // Fused rowptr build (independent work; overlaps prefetch latency).
    {
        int g = blockIdx.x * 256 + tid;
        rowptr_group(dst, g);
        int g2 = g + GEMM_NTHREAD;
        if (g2 < N_GROUPS) rowptr_group(dst, g2);
    }

#pragma unroll 1
    for (int kb = 0; kb < D_IN / BKT; kb++) {
#pragma unroll
        for (int i = 0; i < 8; i++) {
            int idx = tid + i * 256;
            int ar  = idx >> 4;
            int ac  = (idx & 15) * 4;
            *(uint2*)&As[ar][ac] = aH[i];
            int br  = idx >> 5;
            int bc  = (idx & 31) * 4;
            *(uint2*)&Bs[br][bc] = bH[i];
        }
        __syncthreads();

        if (kb + 1 < D_IN / BKT) {
            int k0 = (kb + 1) * BKT;
#pragma unroll
            for (int i = 0; i < 8; i++) {
                int idx = tid + i * 256;
                int ar  = idx >> 4;
                int ac4 = idx & 15;
                int grow = block_row + ar;
                float4 a = (grow < N_NODES)
                    ? *(const float4*)&X[(size_t)grow * D_IN + k0 + ac4 * 4]
                    : make_float4(0.f, 0.f, 0.f, 0.f);
                aH[i] = f4_to_h4(a);
                int br  = idx >> 5;
                int bc4 = idx & 31;
                bH[i] = f4_to_h4(*(const float4*)&W[(size_t)(k0 + br) * D_OUT + bc4 * 4]);
            }
        }

#pragma unroll
        for (int ks = 0; ks < 4; ks++) {
            const int k0 = ks * 16;

            uint32_t af[2][4];
#pragma unroll
            for (int mt = 0; mt < 2; mt++) {
                const __half* p =
                    &As[warp_m + mt * 16 + (quad & 1) * 8 + rin][k0 + (quad >> 1) * 8];
                ldm_x4(af[mt], p);
            }

            uint32_t bf[8][2];
#pragma unroll
            for (int np = 0; np < 4; np++) {
                uint32_t r[4];
                const __half* p =
                    &Bs[k0 + (quad & 1) * 8 + rin][warp_n + np * 16 + (quad >> 1) * 8];
                ldm_x4_trans(r, p);
                bf[np * 2    ][0] = r[0];
                bf[np * 2    ][1] = r[1];
                bf[np * 2 + 1][0] = r[2];
                bf[np * 2 + 1][1] = r[3];
            }

#pragma unroll
            for (int nt = 0; nt < 8; nt++) {
                mma_f16(acc[0][nt], af[0], bf[nt][0], bf[nt][1]);
                mma_f16(acc[1][nt], af[1], bf[nt][0], bf[nt][1]);
            }
        }
        __syncthreads();
    }

#pragma unroll
    for (int mt = 0; mt < 2; mt++) {
        int r0 = block_row + warp_m + mt * 16 + lq;
        int r1 = r0 + 8;
#pragma unroll
        for (int nt = 0; nt < 8; nt++) {
            int c = warp_n + nt * 8 + lr * 2;
            if (r0 < N_NODES)
                *(__half2*)&g_support[(size_t)r0 * D_OUT + c] =
                    __floats2half2_rn(acc[mt][nt][0], acc[mt][nt][1]);
            if (r1 < N_NODES)
                *(__half2*)&g_support[(size_t)r1 * D_OUT + c] =
                    __floats2half2_rn(acc[mt][nt][2], acc[mt][nt][3]);
        }
    }
}

// ---------------------------------------------------------------------------
// Kernel 2: CSR SpMM — instruction-count reduction (R14 ncu: issue-bound,
// L2 only 31%).  Changes vs R14:
//  * per-row loop aligned to 4-edge boundaries -> int4/float4 metadata loads
//    (2x LDG.128 instead of 8x LDG.32 per batch)
//  * gather bounds-guards removed (indices proven in-range)
//  * 32-bit element-offset addressing (one IMAD.WIDE per gather)
// ---------------------------------------------------------------------------
__device__ __forceinline__ void edge_accum(float4& acc, uint2 g, float v) {
    float2 f0 = __half22float2(*(const __half2*)&g.x);
    float2 f1 = __half22float2(*(const __half2*)&g.y);
    acc.x += v * f0.x;
    acc.y += v * f0.y;
    acc.z += v * f1.x;
    acc.w += v * f1.y;
}

__global__ __launch_bounds__(256) void spmm_csr_kernel(const int* __restrict__ src,
                                                       const float* __restrict__ val,
                                                       const float* __restrict__ bias,
                                                       float* __restrict__ out) {
    const int warp_id = (blockIdx.x * blockDim.x + threadIdx.x) >> 5;
    const int lane    = threadIdx.x & 31;
    const unsigned lane4 = lane * 4;

    if (warp_id >= N_NODES) return;
    const int n  = warp_id;
    const int r0 = g_row_ptr[n];
    const int r1 = g_row_ptr[n + 1];

    const float4 bias4 = *(const float4*)&bias[lane4];
    float4 acc = make_float4(0.f, 0.f, 0.f, 0.f);

    int e = r0;
    // Scalar prologue up to a 4-aligned edge index (<= 3 iterations).
    int e_al = (r0 + 3) & ~3;
    if (e_al > r1) e_al = r1;
    for (; e < e_al; e++) {
        unsigned off = (unsigned)src[e] * D_OUT + lane4;
        uint2 g = *(const uint2*)&g_support[off];
        edge_accum(acc, g, val[e]);
    }
    // Aligned batches of 4: vector metadata + 4 independent gathers (MLP=4).
    for (; e + 4 <= r1; e += 4) {
        const int4   s4 = *(const int4*)&src[e];
        const float4 v4 = *(const float4*)&val[e];

        unsigned o0 = (unsigned)s4.x * D_OUT + lane4;
        unsigned o1 = (unsigned)s4.y * D_OUT + lane4;
        unsigned o2 = (unsigned)s4.z * D_OUT + lane4;
        unsigned o3 = (unsigned)s4.w * D_OUT + lane4;

        uint2 g0 = *(const uint2*)&g_support[o0];
        uint2 g1 = *(const uint2*)&g_support[o1];
        uint2 g2 = *(const uint2*)&g_support[o2];
        uint2 g3 = *(const uint2*)&g_support[o3];

        edge_accum(acc, g0, v4.x);
        edge_accum(acc, g1, v4.y);
        edge_accum(acc, g2, v4.z);
        edge_accum(acc, g3, v4.w);
    }
    // Scalar tail (< 4 edges).
    for (; e < r1; e++) {
        unsigned off = (unsigned)src[e] * D_OUT + lane4;
        uint2 g = *(const uint2*)&g_support[off];
        edge_accum(acc, g, val[e]);
    }

    *(float4*)&out[(size_t)n * D_OUT + lane4] =
        make_float4(acc.x + bias4.x, acc.y + bias4.y,
                    acc.z + bias4.z, acc.w + bias4.w);
}

// ---------------------------------------------------------------------------
// Launch
// Inputs (metadata order): x, adj_src, adj_dst, adj_val, weight, bias
// ---------------------------------------------------------------------------
extern "C" void kernel_launch(void* const* d_in, const int* in_sizes, int n_in,
                              void* d_out, int out_size) {
    const float* x      = (const float*)d_in[0];
    const int*   adjsrc = (const int*)d_in[1];
    const int*   adjdst = (const int*)d_in[2];
    const float* adjval = (const float*)d_in[3];
    const float* weight = (const float*)d_in[4];
    const float* bias   = (const float*)d_in[5];
    float*       out    = (float*)d_out;

    // 1) support = X @ W (fp16 tensor cores) + fused rowptr build
    gemm_tc_kernel<<<GEMM_GRID, 256>>>(x, weight, adjdst);

    // 2) out[n,:] = bias + CSR-row reduction  (one warp per node)
    int n_blocks = (N_NODES * 32 + 255) / 256;   // 6250
    spmm_csr_kernel<<<n_blocks, 256>>>(adjsrc, adjval, bias, out);
}